// round 13
// baseline (speedup 1.0000x reference)
#include <cuda_runtime.h>
#include <cuda_fp16.h>
#include <cstdint>

#define MDIM 8192
#define KDIM 4096
#define NDIM 4096
#define NMB 128   // MDIM/64 mask row-blocks
#define NKB 64    // KDIM/64 mask k-blocks

#define WTILES 16384     // 128x128 W transpose tiles (32x32 each)
#define XBLOCKS 8192     // 64x64 x blocks
#define GTILES 2048      // gemm tiles: 128 bands x 16 N-tiles
#define GRID_P 296       // persistent CTAs (<= 2 per SM on 148-SM part)

// GEMM tiling (R5 core): CTA tile 64(M) x 256(N), 4 warps, warp tile 64x64,
// K-step 64, SW128-swizzled smem, 2-stage cp.async, 2 CTAs/SM.
#define A_STAGE_BYTES (64 * 128)     // 8192
#define B_STAGE_BYTES (256 * 128)    // 32768
#define STAGE_BYTES (A_STAGE_BYTES + B_STAGE_BYTES)  // 40960
#define STAGES 2
#define SMEM_DYN (STAGES * STAGE_BYTES)              // 81920

// Static device scratch.
__device__ __half g_x[(size_t)MDIM * KDIM];      // [M][K], active blocks only (else 0)
__device__ __half g_wt[(size_t)NDIM * KDIM];     // [N][K] (W^T)
__device__ unsigned char g_mask[NMB * 128];      // 128B row stride (exclusive lines)
__device__ int g_widx, g_wdone, g_xidx, g_tidx;
__device__ int g_bandcnt[NMB];

// ---------------------------------------------------------------------------
// helpers
// ---------------------------------------------------------------------------
__device__ __forceinline__ uint32_t smem_u32(const void* p) {
    uint32_t a;
    asm("{ .reg .u64 t; cvta.to.shared.u64 t, %1; cvt.u32.u64 %0, t; }" : "=r"(a) : "l"(p));
    return a;
}
__device__ __forceinline__ void cp16(uint32_t dst, const void* src) {
    asm volatile("cp.async.cg.shared.global [%0], [%1], 16;" :: "r"(dst), "l"(src) : "memory");
}
__device__ __forceinline__ void ldsm4(uint32_t* r, uint32_t addr) {
    asm volatile("ldmatrix.sync.aligned.m8n8.x4.shared.b16 {%0,%1,%2,%3}, [%4];\n"
                 : "=r"(r[0]), "=r"(r[1]), "=r"(r[2]), "=r"(r[3]) : "r"(addr));
}
__device__ __forceinline__ void mma16816(float* c, const uint32_t* a, const uint32_t* b) {
    asm volatile(
        "mma.sync.aligned.m16n8k16.row.col.f32.f16.f16.f32 "
        "{%0,%1,%2,%3}, {%4,%5,%6,%7}, {%8,%9}, {%0,%1,%2,%3};\n"
        : "+f"(c[0]), "+f"(c[1]), "+f"(c[2]), "+f"(c[3])
        : "r"(a[0]), "r"(a[1]), "r"(a[2]), "r"(a[3]), "r"(b[0]), "r"(b[1]));
}

// ---------------------------------------------------------------------------
// init: zero queues/counters (runs every graph replay)
// ---------------------------------------------------------------------------
__global__ void init_kernel() {
    int t = threadIdx.x;
    if (t < NMB) g_bandcnt[t] = 0;
    if (t == 128) g_widx = 0;
    if (t == 129) g_wdone = 0;
    if (t == 130) g_xidx = 0;
    if (t == 131) g_tidx = 0;
}

// ---------------------------------------------------------------------------
// fused persistent kernel: Phase A (W transpose) -> Phase B (x mask+convert,
// band-major) -> Phase C (gemm tiles, dependency-gated work stealing).
// ---------------------------------------------------------------------------
__global__ __launch_bounds__(128, 2) void fused_kernel(
    const float* __restrict__ x, const float* __restrict__ w, float* __restrict__ out) {
    extern __shared__ __align__(1024) char smem[];
    __shared__ __half sT[32][33];
    __shared__ float ws4[4];
    __shared__ int sh_idx;
    __shared__ int sh_active;
    __shared__ unsigned char akb[NKB];
    __shared__ int nact_s;

    const int tid = threadIdx.x, wid = tid >> 5, lane = tid & 31;

    // ================= Phase A: W[K][N] -> g_wt[N][K] fp16 =================
    for (;;) {
        if (tid == 0) sh_idx = atomicAdd(&g_widx, 1);
        __syncthreads();
        int t = sh_idx;
        if (t >= WTILES) break;
        int n0 = (t & 127) * 32, k0 = (t >> 7) * 32;
        int xl = tid & 31, yl = tid >> 5;           // 32 x 4 threads
#pragma unroll
        for (int l = 0; l < 8; l++) {
            int k = yl + l * 4;
            sT[k][xl] = __float2half_rn(w[(size_t)(k0 + k) * NDIM + n0 + xl]);
        }
        __syncthreads();
#pragma unroll
        for (int l = 0; l < 8; l++) {
            int n = yl + l * 4;
            g_wt[(size_t)(n0 + n) * KDIM + k0 + xl] = sT[xl][n];
        }
        __threadfence();
        __syncthreads();
        if (tid == 0) atomicAdd(&g_wdone, 1);
    }

    // ============ Phase B: x mask + fp16 convert (band-major) =============
    for (;;) {
        if (tid == 0) sh_idx = atomicAdd(&g_xidx, 1);
        __syncthreads();
        int t = sh_idx;
        if (t >= XBLOCKS) break;
        int mb = t >> 6, kb = t & 63;
        int r = tid >> 1, q = tid & 1;              // row 0..63, col half
        const float4* xp = (const float4*)(x + (size_t)(mb * 64 + r) * KDIM + kb * 64 + q * 32);
        float4 v[8];
        float s = 0.f;
#pragma unroll
        for (int i = 0; i < 8; i++) {
            v[i] = xp[i];
            s += fabsf(v[i].x) + fabsf(v[i].y) + fabsf(v[i].z) + fabsf(v[i].w);
        }
#pragma unroll
        for (int o = 16; o; o >>= 1) s += __shfl_xor_sync(0xffffffffu, s, o);
        if (lane == 0) ws4[wid] = s;
        __syncthreads();
        if (tid == 0) {
            float tt = ws4[0] + ws4[1] + ws4[2] + ws4[3];
            int a = (tt * (1.0f / 4096.0f)) > 0.8f ? 1 : 0;
            sh_active = a;
            g_mask[mb * 128 + kb] = (unsigned char)a;
        }
        __syncthreads();
        if (sh_active) {
            __half2 h[16];
#pragma unroll
            for (int i = 0; i < 8; i++) {
                h[2 * i + 0] = __floats2half2_rn(v[i].x, v[i].y);
                h[2 * i + 1] = __floats2half2_rn(v[i].z, v[i].w);
            }
            uint4* op = (uint4*)(g_x + (size_t)(mb * 64 + r) * KDIM + kb * 64 + q * 32);
            op[0] = *(uint4*)&h[0];
            op[1] = *(uint4*)&h[4];
            op[2] = *(uint4*)&h[8];
            op[3] = *(uint4*)&h[12];
        }
        __threadfence();
        __syncthreads();
        if (tid == 0) atomicAdd(&g_bandcnt[mb], 1);
    }

    // ================= Phase C: gemm tiles (work stealing) =================
    const uint32_t smem_base = smem_u32(smem);
    const int wn = wid * 64;
    const int a_row = ((lane >> 3) & 1) * 8 + (lane & 7);
    const int a_col2 = ((lane >> 4) * 8) * 2;
    const int b_g = lane >> 3;
    const int b_row = (b_g >> 1) * 8 + (lane & 7);
    const int b_col2 = ((b_g & 1) * 8) * 2;

    uint32_t aRB[4], aSW[4], bRB[4], bSW[4];
#pragma unroll
    for (int mi = 0; mi < 4; mi++) {
        int row = mi * 16 + a_row;
        aRB[mi] = (uint32_t)(row * 128);
        aSW[mi] = (uint32_t)((row & 7) << 4);
    }
#pragma unroll
    for (int p = 0; p < 4; p++) {
        int row = wn + p * 16 + b_row;
        bRB[p] = (uint32_t)(row * 128);
        bSW[p] = (uint32_t)((row & 7) << 4);
    }

    for (;;) {
        if (tid == 0) sh_idx = atomicAdd(&g_tidx, 1);
        __syncthreads();
        int t = sh_idx;
        if (t >= GTILES) break;
        const int mbt = t >> 4, nt = t & 15;

        if (tid == 0) {
            while (atomicAdd(&g_wdone, 0) < WTILES) __nanosleep(128);
            while (atomicAdd(&g_bandcnt[mbt], 0) < 64) __nanosleep(128);
            __threadfence();
            const unsigned char* mrow = g_mask + mbt * 128;
            int n = 0;
            for (int k = 0; k < NKB; k++) if (mrow[k]) akb[n++] = (unsigned char)k;
            nact_s = n;
        }
        __syncthreads();
        const int nact = nact_s;

        if (nact == 0) {
            float4 z = make_float4(0.f, 0.f, 0.f, 0.f);
            for (int i = tid; i < 64 * 64; i += 128) {
                int rr = i >> 6, cc = (i & 63) * 4;
                *(float4*)(out + (size_t)(mbt * 64 + rr) * NDIM + nt * 256 + cc) = z;
            }
            continue;
        }

        float acc[4][8][4];
#pragma unroll
        for (int i = 0; i < 4; i++)
#pragma unroll
            for (int j = 0; j < 8; j++)
#pragma unroll
                for (int c = 0; c < 4; c++) acc[i][j][c] = 0.f;

        const char* gAbase = (const char*)g_x + (size_t)(mbt * 64) * (KDIM * 2);
        const char* gBbase = (const char*)g_wt + (size_t)(nt * 256) * (KDIM * 2);

#define FILL(sidx, kb)                                                          \
    {                                                                           \
        uint32_t sA = smem_base + (sidx) * STAGE_BYTES;                         \
        const char* gA = gAbase + (size_t)(kb) * 128;                           \
        _Pragma("unroll")                                                       \
        for (int tt2 = 0; tt2 < 4; tt2++) {                                     \
            int c = tid + tt2 * 128; int r = c >> 3, q = c & 7;                 \
            cp16(sA + r * 128 + ((q * 16) ^ ((r & 7) << 4)),                    \
                 gA + (size_t)r * (KDIM * 2) + q * 16);                         \
        }                                                                       \
        uint32_t sB = sA + A_STAGE_BYTES;                                       \
        const char* gB = gBbase + (size_t)(kb) * 128;                           \
        _Pragma("unroll")                                                       \
        for (int tt2 = 0; tt2 < 16; tt2++) {                                    \
            int c = tid + tt2 * 128; int r = c >> 3, q = c & 7;                 \
            cp16(sB + r * 128 + ((q * 16) ^ ((r & 7) << 4)),                    \
                 gB + (size_t)r * (KDIM * 2) + q * 16);                         \
        }                                                                       \
    }

        FILL(0, (int)akb[0]);
        asm volatile("cp.async.commit_group;" ::: "memory");
        if (nact > 1) FILL(1, (int)akb[1]);
        asm volatile("cp.async.commit_group;" ::: "memory");

        for (int i = 0; i < nact; i++) {
            asm volatile("cp.async.wait_group 1;" ::: "memory");
            __syncthreads();

            const uint32_t sA_u = smem_base + (i & 1) * STAGE_BYTES;
            const uint32_t sB_u = sA_u + A_STAGE_BYTES;

#pragma unroll
            for (int ks = 0; ks < 4; ks++) {
                const uint32_t k32 = (uint32_t)(ks * 32);
                uint32_t aF[4][4];
                uint32_t bF[8][2];
#pragma unroll
                for (int mi = 0; mi < 4; mi++)
                    ldsm4(aF[mi], sA_u + aRB[mi] + ((k32 + a_col2) ^ aSW[mi]));
#pragma unroll
                for (int p = 0; p < 4; p++) {
                    uint32_t r4[4];
                    ldsm4(r4, sB_u + bRB[p] + ((k32 + b_col2) ^ bSW[p]));
                    bF[p * 2][0] = r4[0]; bF[p * 2][1] = r4[1];
                    bF[p * 2 + 1][0] = r4[2]; bF[p * 2 + 1][1] = r4[3];
                }
#pragma unroll
                for (int mi = 0; mi < 4; mi++)
#pragma unroll
                    for (int nj = 0; nj < 8; nj++)
                        mma16816(acc[mi][nj], aF[mi], bF[nj]);
            }

            __syncthreads();
            const int f = i + STAGES;
            if (f < nact) {
                FILL(i & 1, (int)akb[f]);
            }
            asm volatile("cp.async.commit_group;" ::: "memory");
        }

        asm volatile("cp.async.wait_group 0;" ::: "memory");
        __syncthreads();

        // epilogue: direct fp32 stores
        const int row0 = mbt * 64 + (lane >> 2);
        const int col0 = nt * 256 + wn + (lane & 3) * 2;
#pragma unroll
        for (int mi = 0; mi < 4; mi++) {
#pragma unroll
            for (int nj = 0; nj < 8; nj++) {
                int col = col0 + nj * 8;
                *(float2*)(out + (size_t)(row0 + mi * 16) * NDIM + col) =
                    make_float2(acc[mi][nj][0], acc[mi][nj][1]);
                *(float2*)(out + (size_t)(row0 + mi * 16 + 8) * NDIM + col) =
                    make_float2(acc[mi][nj][2], acc[mi][nj][3]);
            }
        }
#undef FILL
    }
}

// ---------------------------------------------------------------------------
extern "C" void kernel_launch(void* const* d_in, const int* in_sizes, int n_in,
                              void* d_out, int out_size) {
    const float* x = (const float*)d_in[0];       // [8192, 4096]
    const float* w = (const float*)d_in[1];       // [4096, 4096]
    float* out = (float*)d_out;                   // [8192, 4096]

    static int smem_set = 0;
    if (!smem_set) {
        cudaFuncSetAttribute(fused_kernel, cudaFuncAttributeMaxDynamicSharedMemorySize, SMEM_DYN);
        smem_set = 1;
    }

    init_kernel<<<1, 256>>>();
    fused_kernel<<<GRID_P, 128, SMEM_DYN>>>(x, w, out);
}

// round 16
// speedup vs baseline: 1.4187x; 1.4187x over previous
#include <cuda_runtime.h>
#include <cuda_fp16.h>
#include <cstdint>

#define MDIM 8192
#define KDIM 4096
#define NDIM 4096
#define NMB 128   // MDIM/64 mask row-blocks
#define NKB 64    // KDIM/64 mask k-blocks

// GEMM tiling (R5/R12 core): CTA 64(M) x 256(N), 4 warps, warp tile 64x64,
// K-step 64, SW128-swizzled smem, 2-stage cp.async, 2 CTAs/SM.
#define A_STAGE_BYTES (64 * 128)     // 8192
#define B_STAGE_BYTES (256 * 128)    // 32768
#define STAGE_BYTES (A_STAGE_BYTES + B_STAGE_BYTES)  // 40960
#define STAGES 2
#define SMEM_DYN (STAGES * STAGE_BYTES)              // 81920

// Static device scratch: fp16 masked x, fp16 W^T, block mask.
__device__ __half g_x[(size_t)MDIM * KDIM];      // [M][K], only active blocks written
__device__ __half g_wt[(size_t)NDIM * KDIM];     // [N][K] (W^T)
__device__ unsigned char g_mask[NMB * NKB];

// ---------------------------------------------------------------------------
// helpers
// ---------------------------------------------------------------------------
__device__ __forceinline__ uint32_t smem_u32(const void* p) {
    uint32_t a;
    asm("{ .reg .u64 t; cvta.to.shared.u64 t, %1; cvt.u32.u64 %0, t; }" : "=r"(a) : "l"(p));
    return a;
}
__device__ __forceinline__ void cp16(uint32_t dst, const void* src) {
    asm volatile("cp.async.cg.shared.global [%0], [%1], 16;" :: "r"(dst), "l"(src) : "memory");
}
__device__ __forceinline__ void ldsm4(uint32_t* r, uint32_t addr) {
    asm volatile("ldmatrix.sync.aligned.m8n8.x4.shared.b16 {%0,%1,%2,%3}, [%4];\n"
                 : "=r"(r[0]), "=r"(r[1]), "=r"(r[2]), "=r"(r[3]) : "r"(addr));
}
__device__ __forceinline__ void mma16816(float* c, const uint32_t* a, const uint32_t* b) {
    asm volatile(
        "mma.sync.aligned.m16n8k16.row.col.f32.f16.f16.f32 "
        "{%0,%1,%2,%3}, {%4,%5,%6,%7}, {%8,%9}, {%0,%1,%2,%3};\n"
        : "+f"(c[0]), "+f"(c[1]), "+f"(c[2]), "+f"(c[3])
        : "r"(a[0]), "r"(a[1]), "r"(a[2]), "r"(a[3]), "r"(b[0]), "r"(b[1]));
}

// ---------------------------------------------------------------------------
// Kernel 1 (MERGED prepass): blockIdx.x < 8192 -> mask+convert one 64x64
// x-block (unchanged from R12); else -> one 64x64 W transpose tile (NEW:
// 4096 big tiles, full-128B-row writes, 4x fewer blocks).
// ---------------------------------------------------------------------------
__global__ void prepass_kernel(const float* __restrict__ x, const float* __restrict__ w) {
    int bid = blockIdx.x;
    int tid = threadIdx.x;          // 256 threads

    if (bid < 8192) {
        // ---- mask + fp16 convert of x block (mb, kb) ----
        int kb = bid & 63, mb = bid >> 6;
        int r = tid >> 2;
        int q = tid & 3;
        const float4* xp = (const float4*)(x + (size_t)(mb * 64 + r) * KDIM + kb * 64 + q * 16);
        float4 v[4];
        float s = 0.f;
#pragma unroll
        for (int i = 0; i < 4; i++) {
            v[i] = xp[i];
            s += fabsf(v[i].x) + fabsf(v[i].y) + fabsf(v[i].z) + fabsf(v[i].w);
        }
#pragma unroll
        for (int o = 16; o; o >>= 1) s += __shfl_xor_sync(0xffffffffu, s, o);
        __shared__ float ws[8];
        __shared__ int active;
        if ((tid & 31) == 0) ws[tid >> 5] = s;
        __syncthreads();
        if (tid == 0) {
            float t = 0.f;
#pragma unroll
            for (int i = 0; i < 8; i++) t += ws[i];
            int a = (t * (1.0f / 4096.0f)) > 0.8f ? 1 : 0;
            active = a;
            g_mask[mb * NKB + kb] = (unsigned char)a;
        }
        __syncthreads();
        if (!active) return;
        __half2 h[8];
#pragma unroll
        for (int i = 0; i < 4; i++) {
            h[i * 2 + 0] = __floats2half2_rn(v[i].x, v[i].y);
            h[i * 2 + 1] = __floats2half2_rn(v[i].z, v[i].w);
        }
        uint4* o = (uint4*)(g_x + (size_t)(mb * 64 + r) * KDIM + kb * 64 + q * 16);
        o[0] = *(uint4*)&h[0];
        o[1] = *(uint4*)&h[4];
    } else {
        // ---- W[K][N] fp32 -> g_wt[N][K] fp16, 64x64 transpose tile ----
        __shared__ __half sT[64][65];
        int b2 = bid - 8192;                 // 0..4095
        int n0 = (b2 & 63) * 64;
        int k0 = (b2 >> 6) * 64;
        {
            int kr = tid >> 2;               // row (k) 0..63
            int qc = tid & 3;                // 16-col chunk
            const float4* wp = (const float4*)(w + (size_t)(k0 + kr) * NDIM + n0 + qc * 16);
#pragma unroll
            for (int j = 0; j < 4; j++) {
                float4 v = wp[j];
                int c = qc * 16 + j * 4;
                sT[kr][c + 0] = __float2half_rn(v.x);
                sT[kr][c + 1] = __float2half_rn(v.y);
                sT[kr][c + 2] = __float2half_rn(v.z);
                sT[kr][c + 3] = __float2half_rn(v.w);
            }
        }
        __syncthreads();
        {
            int nr = tid >> 2;               // row (n) 0..63
            int qk = tid & 3;                // 16-k chunk
            __half tmp[16];
#pragma unroll
            for (int j = 0; j < 16; j++) tmp[j] = sT[qk * 16 + j][nr];
            uint4* op = (uint4*)(g_wt + (size_t)(n0 + nr) * KDIM + k0 + qk * 16);
            op[0] = *(uint4*)&tmp[0];
            op[1] = *(uint4*)&tmp[8];
        }
    }
}

// ---------------------------------------------------------------------------
// Kernel 2: block-sparse HMMA GEMM (R12 core, unchanged). CTA 64(M) x
// 256(N), 4 warps (1x4), warp tile 64x64 via 4x8 m16n8k16, f32 accum.
// SW128-swizzled smem, 2-stage cp.async double buffer, 2 CTAs/SM.
// ---------------------------------------------------------------------------
__global__ __launch_bounds__(128, 2) void gemm_hmma(float* __restrict__ out) {
    extern __shared__ __align__(1024) char smem[];
    __shared__ unsigned char akb[NKB];
    __shared__ int nact_s;

    const int tid = threadIdx.x, wid = tid >> 5, lane = tid & 31;
    const int nt = blockIdx.x;   // N-tile (256 cols)
    const int mbt = blockIdx.y;  // 64-row band == mask row

    if (tid == 0) {
        const unsigned char* mrow = g_mask + mbt * NKB;
        int n = 0;
        for (int k = 0; k < NKB; k++) if (mrow[k]) akb[n++] = (unsigned char)k;
        nact_s = n;
    }
    __syncthreads();
    const int nact = nact_s;

    // zero-output fast path
    if (nact == 0) {
        float4 z = make_float4(0.f, 0.f, 0.f, 0.f);
        for (int i = tid; i < 64 * 64; i += 128) {
            int rr = i >> 6, cc = (i & 63) * 4;
            *(float4*)(out + (size_t)(mbt * 64 + rr) * NDIM + nt * 256 + cc) = z;
        }
        return;
    }

    const uint32_t smem_base = smem_u32(smem);
    const int wn = wid * 64;     // warp N offset

    float acc[4][8][4];
#pragma unroll
    for (int i = 0; i < 4; i++)
#pragma unroll
        for (int j = 0; j < 8; j++)
#pragma unroll
            for (int c = 0; c < 4; c++) acc[i][j][c] = 0.f;

    // ldmatrix lane address components
    const int a_row = ((lane >> 3) & 1) * 8 + (lane & 7);
    const int a_col2 = ((lane >> 4) * 8) * 2;        // byte offset: 0 or 16
    const int b_g   = lane >> 3;
    const int b_row = (b_g >> 1) * 8 + (lane & 7);
    const int b_col2 = ((b_g & 1) * 8) * 2;          // byte offset: 0 or 16

    uint32_t aRB[4], aSW[4], bRB[4], bSW[4];
#pragma unroll
    for (int mi = 0; mi < 4; mi++) {
        int row = mi * 16 + a_row;
        aRB[mi] = (uint32_t)(row * 128);
        aSW[mi] = (uint32_t)((row & 7) << 4);
    }
#pragma unroll
    for (int p = 0; p < 4; p++) {
        int row = wn + p * 16 + b_row;
        bRB[p] = (uint32_t)(row * 128);
        bSW[p] = (uint32_t)((row & 7) << 4);
    }

    const char* gAbase = (const char*)g_x + (size_t)(mbt * 64) * (KDIM * 2);
    const char* gBbase = (const char*)g_wt + (size_t)(nt * 256) * (KDIM * 2);

    // ---- stage fill: A 512 x 16B, B 2048 x 16B; SW128 swizzle; 128 thr ----
#define FILL(sidx, kb)                                                          \
    {                                                                           \
        uint32_t sA = smem_base + (sidx) * STAGE_BYTES;                         \
        const char* gA = gAbase + (size_t)(kb) * 128;                           \
        _Pragma("unroll")                                                       \
        for (int t = 0; t < 4; t++) {                                           \
            int c = tid + t * 128; int r = c >> 3, q = c & 7;                   \
            cp16(sA + r * 128 + ((q * 16) ^ ((r & 7) << 4)),                    \
                 gA + (size_t)r * (KDIM * 2) + q * 16);                         \
        }                                                                       \
        uint32_t sB = sA + A_STAGE_BYTES;                                       \
        const char* gB = gBbase + (size_t)(kb) * 128;                           \
        _Pragma("unroll")                                                       \
        for (int t = 0; t < 16; t++) {                                          \
            int c = tid + t * 128; int r = c >> 3, q = c & 7;                   \
            cp16(sB + r * 128 + ((q * 16) ^ ((r & 7) << 4)),                    \
                 gB + (size_t)r * (KDIM * 2) + q * 16);                         \
        }                                                                       \
    }

    // prologue: fill both stages
    FILL(0, (int)akb[0]);
    asm volatile("cp.async.commit_group;" ::: "memory");
    if (nact > 1) FILL(1, (int)akb[1]);
    asm volatile("cp.async.commit_group;" ::: "memory");

    for (int i = 0; i < nact; i++) {
        asm volatile("cp.async.wait_group 1;" ::: "memory");
        __syncthreads();

        const uint32_t sA_u = smem_base + (i & 1) * STAGE_BYTES;
        const uint32_t sB_u = sA_u + A_STAGE_BYTES;

#pragma unroll
        for (int ks = 0; ks < 4; ks++) {
            const uint32_t k32 = (uint32_t)(ks * 32);   // byte col base for this k16
            uint32_t aF[4][4];
            uint32_t bF[8][2];
#pragma unroll
            for (int mi = 0; mi < 4; mi++)
                ldsm4(aF[mi], sA_u + aRB[mi] + ((k32 + a_col2) ^ aSW[mi]));
#pragma unroll
            for (int p = 0; p < 4; p++) {
                uint32_t r4[4];
                ldsm4(r4, sB_u + bRB[p] + ((k32 + b_col2) ^ bSW[p]));
                bF[p * 2][0] = r4[0]; bF[p * 2][1] = r4[1];
                bF[p * 2 + 1][0] = r4[2]; bF[p * 2 + 1][1] = r4[3];
            }
#pragma unroll
            for (int mi = 0; mi < 4; mi++)
#pragma unroll
                for (int nj = 0; nj < 8; nj++)
                    mma16816(acc[mi][nj], aF[mi], bF[nj]);
        }

        __syncthreads();
        const int f = i + STAGES;
        if (f < nact) {
            FILL(i & 1, (int)akb[f]);
        }
        asm volatile("cp.async.commit_group;" ::: "memory");
    }

    // ---- epilogue: direct fp32 stores ----
    const int row0 = mbt * 64 + (lane >> 2);
    const int col0 = nt * 256 + wn + (lane & 3) * 2;
#pragma unroll
    for (int mi = 0; mi < 4; mi++) {
#pragma unroll
        for (int nj = 0; nj < 8; nj++) {
            int col = col0 + nj * 8;
            *(float2*)(out + (size_t)(row0 + mi * 16) * NDIM + col) =
                make_float2(acc[mi][nj][0], acc[mi][nj][1]);
            *(float2*)(out + (size_t)(row0 + mi * 16 + 8) * NDIM + col) =
                make_float2(acc[mi][nj][2], acc[mi][nj][3]);
        }
    }
}

// ---------------------------------------------------------------------------
extern "C" void kernel_launch(void* const* d_in, const int* in_sizes, int n_in,
                              void* d_out, int out_size) {
    const float* x = (const float*)d_in[0];       // [8192, 4096]
    const float* w = (const float*)d_in[1];       // [4096, 4096]
    float* out = (float*)d_out;                   // [8192, 4096]

    static int smem_set = 0;
    if (!smem_set) {
        cudaFuncSetAttribute(gemm_hmma, cudaFuncAttributeMaxDynamicSharedMemorySize, SMEM_DYN);
        smem_set = 1;
    }

    prepass_kernel<<<8192 + 4096, 256>>>(x, w);
    gemm_hmma<<<dim3(NDIM / 256, MDIM / 64), 128, SMEM_DYN>>>(out);
}